// round 5
// baseline (speedup 1.0000x reference)
#include <cuda_runtime.h>
#include <cstdint>

#define N_NODES 100000
#define N_EDGES 1600000
#define NG 64
#define OUTD 32
#define NPAD (N_NODES + 128)

// ---------------- static scratch ----------------
__device__ int      g_degs[N_NODES];
__device__ int      g_cnt[N_NODES];
__device__ float    g_dinv[N_NODES];
__device__ int      g_rowptr[N_NODES + 1];
__device__ int      g_cursor[N_NODES];
__device__ int2     g_edge[N_EDGES];
__device__ int      g_is64;

__device__ double   g_bnsum[3 * 64], g_bnss[3 * 64];
__device__ float    g_psum[NG * OUTD];
__device__ unsigned g_pmax[NG * OUTD], g_pmin[NG * OUTD];
__device__ float    g_pcnt[NG];

#define OFF_A4  0
#define OFF_B4  (OFF_A4 + NPAD * 4)
#define OFF_C4  (OFF_B4 + NPAD * 4)
#define OFF_D4  (OFF_C4 + NPAD * 4)
#define OFF_H1  (OFF_D4 + NPAD * 4)
#define OFF_H2  (OFF_H1 + NPAD * 64)
#define OFF_TB  (OFF_H2 + NPAD * 64)
#define OFF_TC  (OFF_TB + NPAD * 64)
#define OFF_TD  (OFF_TC + NPAD * 64)
#define OFF_H4  (OFF_TD + NPAD * 64)
#define POOL_FLOATS (OFF_H4 + NPAD * 32)

__device__ __align__(16) float g_pool[POOL_FLOATS];

// ---------------- helpers ----------------
__device__ __forceinline__ unsigned encf(float f) {
    unsigned u = __float_as_uint(f);
    return (u & 0x80000000u) ? ~u : (u | 0x80000000u);
}
__device__ __forceinline__ float decf(unsigned u) {
    return (u & 0x80000000u) ? __uint_as_float(u & 0x7fffffffu) : __uint_as_float(~u);
}
#define ENC_NEG_INF 0x007fffffu
#define ENC_POS_INF 0xff800000u

__device__ __forceinline__ int read_idx(const void* p, long long i) {
    if (g_is64) return (int)((const long long*)p)[i];
    return ((const int*)p)[i];
}

// tf32 hi/lo split: hi = rna(x), lo = rna(x - hi)
__device__ __forceinline__ void tf32split(float x, uint32_t& hi, uint32_t& lo) {
    uint32_t h;
    asm("cvt.rna.tf32.f32 %0, %1;" : "=r"(h) : "f"(x));
    float r = x - __uint_as_float(h);
    asm("cvt.rna.tf32.f32 %0, %1;" : "=r"(lo) : "f"(r));
    hi = h;
}

__device__ __forceinline__ void mma_tf32(float* c, uint32_t a0, uint32_t a1, uint32_t a2,
                                         uint32_t a3, uint32_t b0, uint32_t b1) {
    asm volatile(
        "mma.sync.aligned.m16n8k8.row.col.f32.tf32.tf32.f32 "
        "{%0,%1,%2,%3}, {%4,%5,%6,%7}, {%8,%9}, {%0,%1,%2,%3};"
        : "+f"(c[0]), "+f"(c[1]), "+f"(c[2]), "+f"(c[3])
        : "r"(a0), "r"(a1), "r"(a2), "r"(a3), "r"(b0), "r"(b1));
}

// ---------------- dtype detection ----------------
__global__ void k_detect(const unsigned* __restrict__ w) {
    if (threadIdx.x == 0 && blockIdx.x == 0) {
        int is64 = 1;
        for (int i = 1; i < 256; i += 2)
            if (w[i] != 0u) { is64 = 0; break; }
        g_is64 = is64;
    }
}

__global__ void k_init() {
    int stride = gridDim.x * blockDim.x;
    for (int i = blockIdx.x * blockDim.x + threadIdx.x; i < N_NODES; i += stride) {
        g_degs[i] = 0;
        g_cnt[i] = 0;
        if (i < 3 * 64) { g_bnsum[i] = 0.0; g_bnss[i] = 0.0; }
        if (i < NG * OUTD) {
            g_psum[i] = 0.0f;
            g_pmax[i] = ENC_NEG_INF;
            g_pmin[i] = ENC_POS_INF;
        }
        if (i < NG) g_pcnt[i] = 0.0f;
    }
}

// ---------------- graph structure ----------------
__global__ void k_deg_cnt(const void* __restrict__ ei) {
    int e = blockIdx.x * blockDim.x + threadIdx.x;
    if (e >= N_EDGES) return;
    int s = read_idx(ei, e);
    int d = read_idx(ei, (long long)N_EDGES + e);
    atomicAdd(&g_degs[s], 1);
    atomicAdd(&g_cnt[d], 1);
}

__global__ void k_dinv() {
    int i = blockIdx.x * blockDim.x + threadIdx.x;
    if (i >= N_NODES) return;
    int d = g_degs[i];
    g_dinv[i] = (d > 0) ? rsqrtf((float)d) : 0.0f;
}

__global__ void k_scan() {
    __shared__ int sums[1024];
    const int CH = (N_NODES + 1023) / 1024;
    int t = threadIdx.x;
    int start = t * CH;
    int end = min(start + CH, N_NODES);
    int s = 0;
    for (int i = start; i < end; i++) s += g_cnt[i];
    sums[t] = s;
    __syncthreads();
    for (int off = 1; off < 1024; off <<= 1) {
        int v = (t >= off) ? sums[t - off] : 0;
        __syncthreads();
        sums[t] += v;
        __syncthreads();
    }
    int excl = t ? sums[t - 1] : 0;
    for (int i = start; i < end; i++) {
        g_rowptr[i] = excl;
        g_cursor[i] = excl;
        excl += g_cnt[i];
    }
    if (t == 1023) g_rowptr[N_NODES] = sums[1023];
}

__global__ void k_fill(const void* __restrict__ ei) {
    int e = blockIdx.x * blockDim.x + threadIdx.x;
    if (e >= N_EDGES) return;
    int s = read_idx(ei, e);
    int d = read_idx(ei, (long long)N_EDGES + e);
    float w = -g_dinv[s] * g_dinv[d];
    int pos = atomicAdd(&g_cursor[d], 1);
    g_edge[pos] = make_int2(s, __float_as_int(w));
}

// ---------------- layer 1 (F=4 padded) ----------------
__global__ void k_copyx(const float* __restrict__ x, float* __restrict__ a4) {
    int n = blockIdx.x * blockDim.x + threadIdx.x;
    if (n >= N_NODES) return;
    float4 v;
    v.x = x[3 * n + 0];
    v.y = x[3 * n + 1];
    v.z = x[3 * n + 2];
    v.w = 0.0f;
    *(float4*)&a4[4 * n] = v;
}

template <bool SUB>
__global__ void k_prop4(const float* __restrict__ hin, const float* __restrict__ sub,
                        float* __restrict__ hout, float scale) {
    int n = blockIdx.x * blockDim.x + threadIdx.x;
    if (n >= N_NODES) return;
    int b = g_rowptr[n], e = g_rowptr[n + 1];
    float4 acc = {0, 0, 0, 0};
    int i = b;
    for (; i + 4 <= e; i += 4) {
        int2 e0 = g_edge[i], e1 = g_edge[i + 1], e2 = g_edge[i + 2], e3 = g_edge[i + 3];
        float4 v0 = *(const float4*)&hin[(size_t)e0.x * 4];
        float4 v1 = *(const float4*)&hin[(size_t)e1.x * 4];
        float4 v2 = *(const float4*)&hin[(size_t)e2.x * 4];
        float4 v3 = *(const float4*)&hin[(size_t)e3.x * 4];
        float w0 = __int_as_float(e0.y), w1 = __int_as_float(e1.y);
        float w2 = __int_as_float(e2.y), w3 = __int_as_float(e3.y);
        acc.x += w0 * v0.x + w1 * v1.x + w2 * v2.x + w3 * v3.x;
        acc.y += w0 * v0.y + w1 * v1.y + w2 * v2.y + w3 * v3.y;
        acc.z += w0 * v0.z + w1 * v1.z + w2 * v2.z + w3 * v3.z;
        acc.w += w0 * v0.w + w1 * v1.w + w2 * v2.w + w3 * v3.w;
    }
    for (; i < e; i++) {
        int2 ed = g_edge[i];
        float w = __int_as_float(ed.y);
        float4 v = *(const float4*)&hin[(size_t)ed.x * 4];
        acc.x += w * v.x; acc.y += w * v.y; acc.z += w * v.z; acc.w += w * v.w;
    }
    float4 o;
    if (SUB) {
        float4 sv = *(const float4*)&sub[(size_t)n * 4];
        o.x = scale * acc.x - sv.x; o.y = scale * acc.y - sv.y;
        o.z = scale * acc.z - sv.z; o.w = scale * acc.w - sv.w;
    } else {
        o.x = scale * acc.x; o.y = scale * acc.y; o.z = scale * acc.z; o.w = scale * acc.w;
    }
    *(float4*)&hout[(size_t)n * 4] = o;
}

// combine1: 64 nodes/block, fused BN stats (layer 0)
__global__ void k_combine1(const float* __restrict__ t0, const float* __restrict__ t1,
                           const float* __restrict__ t2, const float* __restrict__ t3,
                           const float* __restrict__ W, const float* __restrict__ b,
                           float* __restrict__ hout) {
    __shared__ float S[4][256];
    __shared__ float cs[64], css[64];
    int t = threadIdx.x;
    int base = blockIdx.x * 64;
    if (t < 64) { cs[t] = 0.0f; css[t] = 0.0f; }
    {
        int k = t >> 6, idx = t & 63;
        const float* txk = (k == 0) ? t0 : (k == 1) ? t1 : (k == 2) ? t2 : t3;
        ((float4*)S[k])[idx] = ((const float4*)(txk + (size_t)base * 4))[idx];
    }
    __syncthreads();
    int o = t & 63, r4 = t >> 6;
    float wr[4][3];
#pragma unroll
    for (int k = 0; k < 4; k++)
#pragma unroll
        for (int i = 0; i < 3; i++) wr[k][i] = W[(k * 3 + i) * 64 + o];
    float bo = b[o];
    float s = 0.0f, ss = 0.0f;
#pragma unroll
    for (int q = 0; q < 16; q++) {
        int nl = q * 4 + r4;
        int n = base + nl;
        float acc = bo;
#pragma unroll
        for (int k = 0; k < 4; k++)
            acc += S[k][nl * 4 + 0] * wr[k][0] + S[k][nl * 4 + 1] * wr[k][1] +
                   S[k][nl * 4 + 2] * wr[k][2];
        acc = (acc >= 0.0f) ? acc : 0.01f * acc;
        if (n < N_NODES) {
            hout[(size_t)n * 64 + o] = acc;
            s += acc;
            ss += acc * acc;
        }
    }
    atomicAdd(&cs[o], s);
    atomicAdd(&css[o], ss);
    __syncthreads();
    if (t < 64) {
        atomicAdd(&g_bnsum[t], (double)cs[t]);
        atomicAdd(&g_bnss[t], (double)css[t]);
    }
}

// ---------------- F=64 propagation: 2 nodes per warp ----------------
template <bool SUB>
__global__ void k_prop64(const float* __restrict__ hin, const float* __restrict__ sub,
                         float* __restrict__ hout, float scale) {
    int w_id = (blockIdx.x * blockDim.x + threadIdx.x) >> 5;
    int lane = threadIdx.x & 31;
    int half = lane >> 4, hl = lane & 15;
    int n = w_id * 2 + half;
    if (n >= N_NODES) return;
    unsigned hmask = 0xFFFFu << (half * 16);
    int sb = half * 16;
    int b = g_rowptr[n];
    int cnt = g_rowptr[n + 1] - b;
    int ocnt = __shfl_xor_sync(0xffffffffu, cnt, 16);
    int mx = max(cnt, ocnt);
    float4 acc = {0, 0, 0, 0};
    for (int base = 0; base < mx; base += 16) {
        int2 ed = make_int2(0, 0);
        if (base + hl < cnt) ed = g_edge[b + base + hl];
        int m = min(16, cnt - base);
        int j = 0;
        for (; j + 4 <= m; j += 4) {
            int s0 = __shfl_sync(hmask, ed.x, sb + j + 0);
            int s1 = __shfl_sync(hmask, ed.x, sb + j + 1);
            int s2 = __shfl_sync(hmask, ed.x, sb + j + 2);
            int s3 = __shfl_sync(hmask, ed.x, sb + j + 3);
            float w0 = __int_as_float(__shfl_sync(hmask, ed.y, sb + j + 0));
            float w1 = __int_as_float(__shfl_sync(hmask, ed.y, sb + j + 1));
            float w2 = __int_as_float(__shfl_sync(hmask, ed.y, sb + j + 2));
            float w3 = __int_as_float(__shfl_sync(hmask, ed.y, sb + j + 3));
            float4 v0 = *(const float4*)&hin[(size_t)s0 * 64 + hl * 4];
            float4 v1 = *(const float4*)&hin[(size_t)s1 * 64 + hl * 4];
            float4 v2 = *(const float4*)&hin[(size_t)s2 * 64 + hl * 4];
            float4 v3 = *(const float4*)&hin[(size_t)s3 * 64 + hl * 4];
            acc.x += w0 * v0.x + w1 * v1.x + w2 * v2.x + w3 * v3.x;
            acc.y += w0 * v0.y + w1 * v1.y + w2 * v2.y + w3 * v3.y;
            acc.z += w0 * v0.z + w1 * v1.z + w2 * v2.z + w3 * v3.z;
            acc.w += w0 * v0.w + w1 * v1.w + w2 * v2.w + w3 * v3.w;
        }
        for (; j < m; j++) {
            int s0 = __shfl_sync(hmask, ed.x, sb + j);
            float w0 = __int_as_float(__shfl_sync(hmask, ed.y, sb + j));
            float4 v0 = *(const float4*)&hin[(size_t)s0 * 64 + hl * 4];
            acc.x += w0 * v0.x; acc.y += w0 * v0.y;
            acc.z += w0 * v0.z; acc.w += w0 * v0.w;
        }
    }
    float4 o;
    if (SUB) {
        float4 sv = *(const float4*)&sub[(size_t)n * 64 + hl * 4];
        o.x = scale * acc.x - sv.x; o.y = scale * acc.y - sv.y;
        o.z = scale * acc.z - sv.z; o.w = scale * acc.w - sv.w;
    } else {
        o.x = scale * acc.x; o.y = scale * acc.y;
        o.z = scale * acc.z; o.w = scale * acc.w;
    }
    *(float4*)&hout[(size_t)n * 64 + hl * 4] = o;
}

// ---------------- tf32 MMA combine ----------------
// Per block (128 thr, 4 warps): D[128 x FOUT] = sum_k Tx_k[128x64] @ W_k[64xFOUT]
// via m16n8k8 tf32 MMA with hi/lo split (hi*hi + lo*hi + hi*lo).
// Warp w owns rows [w*32, w*32+32). Epilogue: +bias, lrelu, fused BN stats.
template <int FOUT, bool LRELU, int LAYER>
__global__ __launch_bounds__(128, 1) void k_mma_combine(
    const float* __restrict__ t0, const float* __restrict__ t1,
    const float* __restrict__ t2, const float* __restrict__ t3,
    const float* __restrict__ W, const float* __restrict__ bias,
    float* __restrict__ hout) {
    constexpr int NT = FOUT / 8;               // n-tiles per warp
    constexpr int AS = 68;                     // A smem row stride (floats)
    constexpr int WS = (FOUT == 64) ? 72 : 40; // W smem row stride (floats)
    extern __shared__ float sm[];
    float* As = sm;                 // 128 x AS
    float* Ws = sm + 128 * AS;      // 64 x WS
    __shared__ float cs[64], css[64], sbias[64];

    const int tid = threadIdx.x;
    const int wid = tid >> 5, lane = tid & 31;
    const int grp = lane >> 2, tig = lane & 3;
    const int nodeBase = blockIdx.x * 128;

    if (tid < 64) {
        cs[tid] = 0.0f; css[tid] = 0.0f;
        sbias[tid] = (tid < FOUT) ? bias[tid] : 0.0f;
    }

    float acc[2][NT][4];
#pragma unroll
    for (int mt = 0; mt < 2; mt++)
#pragma unroll
        for (int nt = 0; nt < NT; nt++)
#pragma unroll
            for (int q = 0; q < 4; q++) acc[mt][nt][q] = 0.0f;

    const float* txs[4] = {t0, t1, t2, t3};
#pragma unroll
    for (int kc = 0; kc < 4; kc++) {
        __syncthreads();
        // stage A tile: 128 rows x 64 feats (2048 float4)
        {
            const float4* src = (const float4*)(txs[kc] + (size_t)nodeBase * 64);
#pragma unroll
            for (int it = 0; it < 16; it++) {
                int v = tid + it * 128;
                int row = v >> 4, c4 = v & 15;
                *(float4*)&As[row * AS + c4 * 4] = src[v];
            }
        }
        // stage W tile: 64 rows x FOUT (row-major, n contiguous)
        {
            const float4* wsrc = (const float4*)(W + (size_t)kc * 64 * FOUT);
            constexpr int WV = 64 * FOUT / 4;   // 1024 or 512
#pragma unroll
            for (int it = 0; it < WV / 128; it++) {
                int v = tid + it * 128;
                int row = v / (FOUT / 4), c4 = v % (FOUT / 4);
                *(float4*)&Ws[row * WS + c4 * 4] = wsrc[v];
            }
        }
        __syncthreads();

        const int warpRow = wid * 32;
#pragma unroll
        for (int kch = 0; kch < 8; kch++) {
            const int k0 = kch * 8;
            uint32_t ah[2][4], al[2][4];
#pragma unroll
            for (int mt = 0; mt < 2; mt++) {
                int r = warpRow + mt * 16 + grp;
                float x0 = As[r * AS + k0 + tig];
                float x1 = As[(r + 8) * AS + k0 + tig];
                float x2 = As[r * AS + k0 + tig + 4];
                float x3 = As[(r + 8) * AS + k0 + tig + 4];
                tf32split(x0, ah[mt][0], al[mt][0]);
                tf32split(x1, ah[mt][1], al[mt][1]);
                tf32split(x2, ah[mt][2], al[mt][2]);
                tf32split(x3, ah[mt][3], al[mt][3]);
            }
#pragma unroll
            for (int nt = 0; nt < NT; nt++) {
                float w0 = Ws[(k0 + tig) * WS + nt * 8 + grp];
                float w1 = Ws[(k0 + tig + 4) * WS + nt * 8 + grp];
                uint32_t bh0, bl0, bh1, bl1;
                tf32split(w0, bh0, bl0);
                tf32split(w1, bh1, bl1);
#pragma unroll
                for (int mt = 0; mt < 2; mt++) {
                    mma_tf32(acc[mt][nt], ah[mt][0], ah[mt][1], ah[mt][2], ah[mt][3], bh0, bh1);
                    mma_tf32(acc[mt][nt], al[mt][0], al[mt][1], al[mt][2], al[mt][3], bh0, bh1);
                    mma_tf32(acc[mt][nt], ah[mt][0], ah[mt][1], ah[mt][2], ah[mt][3], bl0, bl1);
                }
            }
        }
    }
    __syncthreads();

    // ---- epilogue: bias, lrelu, store, BN stats ----
    float psum[NT][2], pss[NT][2];
#pragma unroll
    for (int nt = 0; nt < NT; nt++) {
        psum[nt][0] = 0.0f; psum[nt][1] = 0.0f;
        pss[nt][0] = 0.0f; pss[nt][1] = 0.0f;
    }
#pragma unroll
    for (int mt = 0; mt < 2; mt++) {
        int r0 = nodeBase + wid * 32 + mt * 16 + grp;
        int r1 = r0 + 8;
        bool v0 = r0 < N_NODES, v1 = r1 < N_NODES;
#pragma unroll
        for (int nt = 0; nt < NT; nt++) {
            int c0 = nt * 8 + tig * 2;
            float e00 = acc[mt][nt][0] + sbias[c0];
            float e01 = acc[mt][nt][1] + sbias[c0 + 1];
            float e10 = acc[mt][nt][2] + sbias[c0];
            float e11 = acc[mt][nt][3] + sbias[c0 + 1];
            if (LRELU) {
                e00 = (e00 >= 0.0f) ? e00 : 0.01f * e00;
                e01 = (e01 >= 0.0f) ? e01 : 0.01f * e01;
                e10 = (e10 >= 0.0f) ? e10 : 0.01f * e10;
                e11 = (e11 >= 0.0f) ? e11 : 0.01f * e11;
            }
            if (v0) *(float2*)&hout[(size_t)r0 * FOUT + c0] = make_float2(e00, e01);
            else { e00 = 0.0f; e01 = 0.0f; }
            if (v1) *(float2*)&hout[(size_t)r1 * FOUT + c0] = make_float2(e10, e11);
            else { e10 = 0.0f; e11 = 0.0f; }
            if (LRELU) {
                psum[nt][0] += e00 + e10;
                psum[nt][1] += e01 + e11;
                pss[nt][0] += e00 * e00 + e10 * e10;
                pss[nt][1] += e01 * e01 + e11 * e11;
            }
        }
    }
    if (LRELU) {
#pragma unroll
        for (int nt = 0; nt < NT; nt++) {
#pragma unroll
            for (int p = 0; p < 2; p++) {
                float s = psum[nt][p], q = pss[nt][p];
#pragma unroll
                for (int off = 4; off < 32; off <<= 1) {
                    s += __shfl_xor_sync(0xffffffffu, s, off);
                    q += __shfl_xor_sync(0xffffffffu, q, off);
                }
                if (grp == 0) {
                    atomicAdd(&cs[nt * 8 + tig * 2 + p], s);
                    atomicAdd(&css[nt * 8 + tig * 2 + p], q);
                }
            }
        }
        __syncthreads();
        if (tid < FOUT) {
            atomicAdd(&g_bnsum[LAYER * 64 + tid], (double)cs[tid]);
            atomicAdd(&g_bnss[LAYER * 64 + tid], (double)css[tid]);
        }
    }
}

// ---------------- batch-norm apply ----------------
__global__ void k_bnapply(float* __restrict__ h, const float* __restrict__ g,
                          const float* __restrict__ bt, int layer) {
    __shared__ float sc[64], sh[64];
    int t = threadIdx.x;
    if (t < 64) {
        double mu = g_bnsum[layer * 64 + t] / (double)N_NODES;
        double var = g_bnss[layer * 64 + t] / (double)N_NODES - mu * mu;
        if (var < 0.0) var = 0.0;
        double inv = rsqrt(var + 1e-5);
        sc[t] = (float)((double)g[t] * inv);
        sh[t] = (float)((double)bt[t] - mu * (double)g[t] * inv);
    }
    __syncthreads();
    int total = N_NODES * 16;
    int stride = gridDim.x * blockDim.x;
    for (int idx = blockIdx.x * blockDim.x + threadIdx.x; idx < total; idx += stride) {
        int c4 = (idx & 15) * 4;
        float4 v = ((float4*)h)[idx];
        v.x = v.x * sc[c4 + 0] + sh[c4 + 0];
        v.y = v.y * sc[c4 + 1] + sh[c4 + 1];
        v.z = v.z * sc[c4 + 2] + sh[c4 + 2];
        v.w = v.w * sc[c4 + 3] + sh[c4 + 3];
        ((float4*)h)[idx] = v;
    }
}

// ---------------- normalize + pooling ----------------
__global__ void k_norm_pool(const float* __restrict__ h, const void* __restrict__ batch) {
    int n = (blockIdx.x * blockDim.x + threadIdx.x) >> 5;
    if (n >= N_NODES) return;
    int lane = threadIdx.x & 31;
    float v = h[(size_t)n * 32 + lane];
    float sq = v * v;
#pragma unroll
    for (int o = 16; o; o >>= 1) sq += __shfl_xor_sync(0xffffffffu, sq, o);
    float norm = fmaxf(sqrtf(sq), 1e-12f);
    v = v / norm;
    int gidx = read_idx(batch, n);
    atomicAdd(&g_psum[gidx * 32 + lane], v);
    atomicMax(&g_pmax[gidx * 32 + lane], encf(v));
    atomicMin(&g_pmin[gidx * 32 + lane], encf(v));
    if (lane == 0) atomicAdd(&g_pcnt[gidx], 1.0f);
}

__global__ void k_finalize(float* __restrict__ out) {
    int idx = blockIdx.x * blockDim.x + threadIdx.x;
    if (idx >= NG * 32) return;
    int g = idx >> 5, c = idx & 31;
    float s = g_psum[g * 32 + c];
    float cnt = fmaxf(g_pcnt[g], 1.0f);
    out[g * 128 + c] = s / cnt;
    out[g * 128 + 32 + c] = decf(g_pmax[g * 32 + c]);
    out[g * 128 + 64 + c] = decf(g_pmin[g * 32 + c]);
    out[g * 128 + 96 + c] = s;
}

// ---------------- host ----------------
extern "C" void kernel_launch(void* const* d_in, const int* in_sizes, int n_in,
                              void* d_out, int out_size) {
    const float* x  = (const float*)d_in[0];
    const void* ei  = d_in[1];
    const void* bat = d_in[2];
    const float* W1 = (const float*)d_in[3];  const float* bc1 = (const float*)d_in[4];
    const float* W2 = (const float*)d_in[5];  const float* bc2 = (const float*)d_in[6];
    const float* W3 = (const float*)d_in[7];  const float* bc3 = (const float*)d_in[8];
    const float* W4 = (const float*)d_in[9];  const float* bc4 = (const float*)d_in[10];
    const float* g1 = (const float*)d_in[11]; const float* bt1 = (const float*)d_in[12];
    const float* g2 = (const float*)d_in[13]; const float* bt2 = (const float*)d_in[14];
    const float* g3 = (const float*)d_in[15]; const float* bt3 = (const float*)d_in[16];
    float* out = (float*)d_out;

    void* poolv = nullptr;
    cudaGetSymbolAddress(&poolv, g_pool);
    float* pool = (float*)poolv;
    float* A4 = pool + OFF_A4;
    float* B4 = pool + OFF_B4;
    float* C4 = pool + OFF_C4;
    float* D4 = pool + OFF_D4;
    float* H1 = pool + OFF_H1;
    float* H2 = pool + OFF_H2;
    float* TB = pool + OFF_TB;
    float* TC = pool + OFF_TC;
    float* TD = pool + OFF_TD;
    float* H4 = pool + OFF_H4;

    const int NB_N  = (N_NODES + 255) / 256;
    const int NB_E  = (N_EDGES + 255) / 256;
    const int NB_W2 = (N_NODES / 2 * 32 + 255) / 256;
    const int NB_W  = (N_NODES * 32 + 255) / 256;
    const int NB_M  = (N_NODES + 127) / 128;

    const int SMEM64 = (128 * 68 + 64 * 72) * 4;   // 53248 B
    const int SMEM32 = (128 * 68 + 64 * 40) * 4;   // 45056 B

    cudaFuncSetAttribute(k_mma_combine<64, true, 1>,
                         cudaFuncAttributeMaxDynamicSharedMemorySize, SMEM64);
    cudaFuncSetAttribute(k_mma_combine<64, true, 2>,
                         cudaFuncAttributeMaxDynamicSharedMemorySize, SMEM64);
    cudaFuncSetAttribute(k_mma_combine<32, false, 3>,
                         cudaFuncAttributeMaxDynamicSharedMemorySize, SMEM32);

    // --- dtype probe + graph structure ---
    k_detect<<<1, 32>>>((const unsigned*)ei);
    k_init<<<512, 256>>>();
    k_deg_cnt<<<NB_E, 256>>>(ei);
    k_dinv<<<NB_N, 256>>>();
    k_scan<<<1, 1024>>>();
    k_fill<<<NB_E, 256>>>(ei);

    // --- layer 1: 3 -> 64 ---
    k_copyx<<<NB_N, 256>>>(x, A4);
    k_prop4<false><<<NB_N, 256>>>(A4, nullptr, B4, 1.0f);
    k_prop4<true><<<NB_N, 256>>>(B4, A4, C4, 2.0f);
    k_prop4<true><<<NB_N, 256>>>(C4, B4, D4, 2.0f);
    k_combine1<<<(N_NODES + 63) / 64, 256>>>(A4, B4, C4, D4, W1, bc1, H1);
    k_bnapply<<<1024, 256>>>(H1, g1, bt1, 0);

    // --- layer 2: 64 -> 64 ---
    k_prop64<false><<<NB_W2, 256>>>(H1, nullptr, TB, 1.0f);
    k_prop64<true><<<NB_W2, 256>>>(TB, H1, TC, 2.0f);
    k_prop64<true><<<NB_W2, 256>>>(TC, TB, TD, 2.0f);
    k_mma_combine<64, true, 1><<<NB_M, 128, SMEM64>>>(H1, TB, TC, TD, W2, bc2, H2);
    k_bnapply<<<1024, 256>>>(H2, g2, bt2, 1);

    // --- layer 3: 64 -> 64 ---
    k_prop64<false><<<NB_W2, 256>>>(H2, nullptr, TB, 1.0f);
    k_prop64<true><<<NB_W2, 256>>>(TB, H2, TC, 2.0f);
    k_prop64<true><<<NB_W2, 256>>>(TC, TB, TD, 2.0f);
    k_mma_combine<64, true, 2><<<NB_M, 128, SMEM64>>>(H2, TB, TC, TD, W3, bc3, H1);
    k_bnapply<<<1024, 256>>>(H1, g3, bt3, 2);

    // --- layer 4: 64 -> 32 ---
    k_prop64<false><<<NB_W2, 256>>>(H1, nullptr, TB, 1.0f);
    k_prop64<true><<<NB_W2, 256>>>(TB, H1, TC, 2.0f);
    k_prop64<true><<<NB_W2, 256>>>(TC, TB, TD, 2.0f);
    k_mma_combine<32, false, 3><<<NB_M, 128, SMEM32>>>(H1, TB, TC, TD, W4, bc4, H4);

    // --- normalize + pool ---
    k_norm_pool<<<NB_W, 256>>>(H4, bat);
    k_finalize<<<(NG * 32 + 255) / 256, 256>>>(out);
}